// round 5
// baseline (speedup 1.0000x reference)
#include <cuda_runtime.h>
#include <math.h>
#include <stdint.h>

#define NNODE 16384
#define NEDGE 1048576
#define NLOOP (NEDGE + NNODE)
#define NIN 256
#define NHID 64
#define LDZ 68    // padded tf32 smem stride
#define LDS 132   // output staging stride: multiple of 4 floats -> 16B-aligned rows

// ---------------- scratch (static device memory; no runtime alloc) ----------
__device__ int   g_cnt[NNODE];
__device__ int   g_rowptr[NNODE + 1];
__device__ int   g_off[NNODE];
__device__ int   g_col[NLOOP];
__device__ float g_dinv[NNODE];
__device__ float g_t[NNODE * NIN];
__device__ float g_h[NNODE * NHID];
__device__ float g_z[NNODE * NHID];

// ---------------- ptx helpers ----------------
__device__ __forceinline__ float to_tf32(float x) {
    uint32_t u;
    asm("cvt.rna.tf32.f32 %0, %1;" : "=r"(u) : "f"(x));
    return __uint_as_float(u);
}
__device__ __forceinline__ void ldsm_x4(uint32_t r[4], uint32_t addr) {
    asm volatile("ldmatrix.sync.aligned.m8n8.x4.shared.b16 {%0,%1,%2,%3}, [%4];"
                 : "=r"(r[0]), "=r"(r[1]), "=r"(r[2]), "=r"(r[3]) : "r"(addr));
}
__device__ __forceinline__ void mma_tf32(float c[4], const uint32_t a[4],
                                         uint32_t b0, uint32_t b1) {
    asm volatile(
        "mma.sync.aligned.m16n8k8.row.col.f32.tf32.tf32.f32 "
        "{%0,%1,%2,%3},{%4,%5,%6,%7},{%8,%9},{%0,%1,%2,%3};"
        : "+f"(c[0]), "+f"(c[1]), "+f"(c[2]), "+f"(c[3])
        : "r"(a[0]), "r"(a[1]), "r"(a[2]), "r"(a[3]), "r"(b0), "r"(b1));
}

// ---------------- CSR build ----------------
__global__ void k_init_cnt() {
    int i = blockIdx.x * blockDim.x + threadIdx.x;
    if (i < NNODE) g_cnt[i] = 1;  // self-loop
}

__global__ void k_hist(const int* __restrict__ ei) {
    int e = blockIdx.x * blockDim.x + threadIdx.x;
    if (e < NEDGE) atomicAdd(&g_cnt[ei[NEDGE + e]], 1);  // dst row
}

__global__ void k_scan() {
    __shared__ int s[1024];
    int tid = threadIdx.x;
    int base = tid * 16;
    int v[16];
    int tot = 0;
#pragma unroll
    for (int j = 0; j < 16; j++) { v[j] = g_cnt[base + j]; tot += v[j]; }
    s[tid] = tot;
    __syncthreads();
    for (int o = 1; o < 1024; o <<= 1) {
        int add = (tid >= o) ? s[tid - o] : 0;
        __syncthreads();
        s[tid] += add;
        __syncthreads();
    }
    int run = (tid == 0) ? 0 : s[tid - 1];
#pragma unroll
    for (int j = 0; j < 16; j++) {
        g_rowptr[base + j] = run;
        g_off[base + j] = run;
        g_dinv[base + j] = rsqrtf((float)v[j]);
        run += v[j];
    }
    if (tid == 1023) g_rowptr[NNODE] = s[1023];
}

__global__ void k_scatter(const int* __restrict__ ei) {
    int idx = blockIdx.x * blockDim.x + threadIdx.x;
    if (idx >= NLOOP) return;
    int s, d;
    if (idx < NEDGE) { s = ei[idx]; d = ei[NEDGE + idx]; }
    else             { s = idx - NEDGE; d = s; }
    int p = atomicAdd(&g_off[d], 1);
    g_col[p] = s;
}

// ---------------- dense GEMM: C[M,NC] = A[M,K] @ W[K,NC] (+bias,relu) -------
template <int K, int NC, bool EPI>
__global__ void k_gemm_nn(const float* __restrict__ A, const float* __restrict__ W,
                          float* __restrict__ C, const float* __restrict__ bias) {
    __shared__ float As[32][68];
    __shared__ float Bs[32][64];
    const int tx = threadIdx.x & 15, ty = threadIdx.x >> 4;
    const int bm = blockIdx.y * 64, bn = blockIdx.x * 64;
    float acc[4][4] = {};
    for (int k0 = 0; k0 < K; k0 += 32) {
#pragma unroll
        for (int i = 0; i < 2; i++) {
            int idx = threadIdx.x + i * 256;
            int r = idx >> 3, kc = (idx & 7) * 4;
            float4 v = *(const float4*)&A[(bm + r) * K + k0 + kc];
            As[kc + 0][r] = v.x; As[kc + 1][r] = v.y;
            As[kc + 2][r] = v.z; As[kc + 3][r] = v.w;
        }
#pragma unroll
        for (int i = 0; i < 2; i++) {
            int idx = threadIdx.x + i * 256;
            int r = idx >> 4, c = (idx & 15) * 4;
            *(float4*)&Bs[r][c] = *(const float4*)&W[(k0 + r) * NC + bn + c];
        }
        __syncthreads();
#pragma unroll
        for (int kk = 0; kk < 32; kk++) {
            float a[4], b[4];
            *(float4*)a = *(const float4*)&As[kk][ty * 4];
            *(float4*)b = *(const float4*)&Bs[kk][tx * 4];
#pragma unroll
            for (int i = 0; i < 4; i++)
#pragma unroll
                for (int j = 0; j < 4; j++) acc[i][j] += a[i] * b[j];
        }
        __syncthreads();
    }
#pragma unroll
    for (int i = 0; i < 4; i++) {
        float4 o;
        float* po = (float*)&o;
#pragma unroll
        for (int j = 0; j < 4; j++) {
            float v = acc[i][j];
            if (EPI) v = fmaxf(v + bias[bn + tx * 4 + j], 0.f);
            po[j] = v;
        }
        if (EPI)
            __stcs((float4*)&C[(bm + ty * 4 + i) * NC + bn + tx * 4], o);
        else
            *(float4*)&C[(bm + ty * 4 + i) * NC + bn + tx * 4] = o;
    }
}

// ---------------- CSR aggregation (+ optional bias + relu) ------------------
template <int F, bool BR>
__global__ void k_agg(const float* __restrict__ t, const float* __restrict__ bias,
                      float* __restrict__ out) {
    int warp = (blockIdx.x * blockDim.x + threadIdx.x) >> 5;
    int lane = threadIdx.x & 31;
    if (warp >= NNODE) return;
    int e = g_rowptr[warp], end = g_rowptr[warp + 1];
    float acc[F / 32] = {};
    for (; e < end; e++) {
        int s = __ldg(&g_col[e]);
        float w = __ldg(&g_dinv[s]);
        const float* row = t + s * F;
#pragma unroll
        for (int j = 0; j < F / 32; j++) acc[j] += w * __ldg(&row[lane + 32 * j]);
    }
    float di = __ldg(&g_dinv[warp]);
#pragma unroll
    for (int j = 0; j < F / 32; j++) {
        float v = acc[j] * di;
        if (BR) v = fmaxf(v + __ldg(&bias[lane + 32 * j]), 0.f);
        out[warp * F + lane + 32 * j] = v;
    }
}

// ---------------- z @ z.T via tf32 mma (symmetric, lower-tri compute) -------
// 128x128 tile per block, 8 warps (4x2), warp tile 32x64, K=64.
__global__ void k_zzt_mma(const float* __restrict__ Z, float* __restrict__ C) {
    const int ti = blockIdx.y, tj = blockIdx.x;
    if (tj > ti) return;
    extern __shared__ float sm[];
    float* Za = sm;              // [128][LDZ]
    float* Zb = sm + 128 * LDZ;  // [128][LDZ]
    const int tid = threadIdx.x;
    const int lane = tid & 31, warp = tid >> 5;
    const int wm = warp >> 1, wn = warp & 1;
    const int m0 = wm * 32, n0 = wn * 64;

#pragma unroll
    for (int i = 0; i < 8; i++) {
        int idx = tid + i * 256;  // 2048 float4s per tile
        int r = idx >> 4, c = (idx & 15) * 4;
        float4 va = *(const float4*)&Z[(ti * 128 + r) * 64 + c];
        float4 vb = *(const float4*)&Z[(tj * 128 + r) * 64 + c];
        Za[r * LDZ + c + 0] = to_tf32(va.x); Za[r * LDZ + c + 1] = to_tf32(va.y);
        Za[r * LDZ + c + 2] = to_tf32(va.z); Za[r * LDZ + c + 3] = to_tf32(va.w);
        Zb[r * LDZ + c + 0] = to_tf32(vb.x); Zb[r * LDZ + c + 1] = to_tf32(vb.y);
        Zb[r * LDZ + c + 2] = to_tf32(vb.z); Zb[r * LDZ + c + 3] = to_tf32(vb.w);
    }
    __syncthreads();

    uint32_t a_base = (uint32_t)__cvta_generic_to_shared(Za);
    uint32_t b_base = (uint32_t)__cvta_generic_to_shared(Zb);
    float acc[2][8][4] = {};
#pragma unroll
    for (int ks = 0; ks < 8; ks++) {
        const int k0 = ks * 8;
        uint32_t a[2][4];
#pragma unroll
        for (int f = 0; f < 2; f++) {
            int r = m0 + f * 16 + (lane & 7) + ((lane & 8) ? 8 : 0);
            int kk = k0 + ((lane & 16) ? 4 : 0);
            ldsm_x4(a[f], a_base + (uint32_t)(r * LDZ + kk) * 4u);
        }
        uint32_t b[4][4];
#pragma unroll
        for (int p = 0; p < 4; p++) {
            int r = n0 + p * 16 + (lane & 7) + ((lane & 16) ? 8 : 0);
            int kk = k0 + ((lane & 8) ? 4 : 0);
            ldsm_x4(b[p], b_base + (uint32_t)(r * LDZ + kk) * 4u);
        }
#pragma unroll
        for (int f = 0; f < 2; f++)
#pragma unroll
            for (int j = 0; j < 8; j++)
                mma_tf32(acc[f][j], a[f], b[j >> 1][(j & 1) * 2], b[j >> 1][(j & 1) * 2 + 1]);
    }
    __syncthreads();  // smem tiles dead; reuse for output staging

    // stage output tile in smem, then fully-coalesced float4 streaming stores
    float(*S)[LDS] = (float(*)[LDS])sm;  // 128 x 132 x 4 = 67584 B <= 69632 B
    const int mrow = lane >> 2, ncol2 = (lane & 3) * 2;
#pragma unroll
    for (int f = 0; f < 2; f++) {
        int r = m0 + f * 16 + mrow;
#pragma unroll
        for (int j = 0; j < 8; j++) {
            int c = n0 + j * 8 + ncol2;
            S[r][c] = acc[f][j][0];     S[r][c + 1] = acc[f][j][1];
            S[r + 8][c] = acc[f][j][2]; S[r + 8][c + 1] = acc[f][j][3];
        }
    }
    __syncthreads();

    // direct tile (ti, tj): row-major coalesced (S rows are 16B-aligned: LDS%4==0)
#pragma unroll
    for (int i = 0; i < 16; i++) {
        int idx = tid + i * 256;          // 4096 float4s
        int y = idx >> 5, xc = (idx & 31) * 4;
        float4 v = *(const float4*)&S[y][xc];
        __stcs((float4*)&C[(size_t)(ti * 128 + y) * NNODE + tj * 128 + xc], v);
    }
    if (ti == tj) return;

    // mirror tile (tj, ti): transposed (scalar) read from smem, coalesced store
#pragma unroll
    for (int i = 0; i < 16; i++) {
        int idx = tid + i * 256;
        int y = idx >> 5, xc = (idx & 31) * 4;
        float4 v = make_float4(S[xc][y], S[xc + 1][y], S[xc + 2][y], S[xc + 3][y]);
        __stcs((float4*)&C[(size_t)(tj * 128 + y) * NNODE + ti * 128 + xc], v);
    }
}

// ---------------- launch ----------------------------------------------------
extern "C" void kernel_launch(void* const* d_in, const int* in_sizes, int n_in,
                              void* d_out, int out_size) {
    const float* x  = (const float*)d_in[0];
    const int*   ei = (const int*)d_in[1];
    const float* W1 = (const float*)d_in[2];
    const float* b1 = (const float*)d_in[3];
    const float* W2 = (const float*)d_in[4];
    const float* b2 = (const float*)d_in[5];
    const float* Wd = (const float*)d_in[6];
    const float* bd = (const float*)d_in[7];
    float* out = (float*)d_out;
    float* xhat = out + (size_t)NNODE * NNODE;

    float* t; cudaGetSymbolAddress((void**)&t, g_t);
    float* h; cudaGetSymbolAddress((void**)&h, g_h);
    float* z; cudaGetSymbolAddress((void**)&z, g_z);

    const int zzt_smem = 2 * 128 * LDZ * (int)sizeof(float);  // 69632
    cudaFuncSetAttribute(k_zzt_mma, cudaFuncAttributeMaxDynamicSharedMemorySize,
                         zzt_smem);

    // one-time side resources (no device memory)
    struct Res {
        cudaStream_t sB;
        cudaEvent_t evA, evB, evC, evD;
        Res() {
            cudaStreamCreateWithFlags(&sB, cudaStreamNonBlocking);
            cudaEventCreateWithFlags(&evA, cudaEventDisableTiming);
            cudaEventCreateWithFlags(&evB, cudaEventDisableTiming);
            cudaEventCreateWithFlags(&evC, cudaEventDisableTiming);
            cudaEventCreateWithFlags(&evD, cudaEventDisableTiming);
        }
    };
    static Res R;

    // ---- fork: CSR build on sB, concurrent with x@W1 on main stream ----
    cudaEventRecord(R.evA, 0);
    cudaStreamWaitEvent(R.sB, R.evA, 0);
    k_init_cnt<<<NNODE / 256, 256, 0, R.sB>>>();
    k_hist<<<NEDGE / 256, 256, 0, R.sB>>>(ei);
    k_scan<<<1, 1024, 0, R.sB>>>();
    k_scatter<<<(NLOOP + 255) / 256, 256, 0, R.sB>>>(ei);
    cudaEventRecord(R.evB, R.sB);

    k_gemm_nn<NIN, NHID, false><<<dim3(1, NNODE / 64), 256>>>(x, W1, t, nullptr);

    // ---- join: encoder chain needs CSR + t ----
    cudaStreamWaitEvent(0, R.evB, 0);
    k_agg<NHID, true><<<NNODE * 32 / 256, 256>>>(t, b1, h);
    k_gemm_nn<NHID, NHID, false><<<dim3(1, NNODE / 64), 256>>>(h, W2, t, nullptr);
    k_agg<NHID, true><<<NNODE * 32 / 256, 256>>>(t, b2, z);

    // ---- fork: attribute decoder on sB, concurrent with z@z.T ----
    cudaEventRecord(R.evC, 0);
    cudaStreamWaitEvent(R.sB, R.evC, 0);
    k_agg<NHID, false><<<NNODE * 32 / 256, 256, 0, R.sB>>>(z, nullptr, t);
    k_gemm_nn<NHID, NIN, true><<<dim3(NIN / 64, NNODE / 64), 256, 0, R.sB>>>(t, Wd, xhat, bd);
    cudaEventRecord(R.evD, R.sB);

    k_zzt_mma<<<dim3(NNODE / 128, NNODE / 128), 256, zzt_smem>>>(z, out);

    // ---- join before returning to harness ----
    cudaStreamWaitEvent(0, R.evD, 0);
}

// round 6
// speedup vs baseline: 1.2080x; 1.2080x over previous
#include <cuda_runtime.h>
#include <math.h>
#include <stdint.h>

#define NNODE 16384
#define NEDGE 1048576
#define NLOOP (NEDGE + NNODE)
#define NIN 256
#define NHID 64
#define LDZ 68   // padded tf32 smem stride (68 mod 32 = 4 -> ldmatrix conflict-free)

// ---------------- scratch (static device memory; no runtime alloc) ----------
__device__ int   g_cnt[NNODE];
__device__ int   g_rowptr[NNODE + 1];
__device__ int   g_off[NNODE];
__device__ int   g_col[NLOOP];
__device__ float g_dinv[NNODE];
__device__ float g_t[NNODE * NIN];
__device__ float g_h[NNODE * NHID];
__device__ float g_z[NNODE * NHID];

// ---------------- ptx helpers ----------------
__device__ __forceinline__ float to_tf32(float x) {
    uint32_t u;
    asm("cvt.rna.tf32.f32 %0, %1;" : "=r"(u) : "f"(x));
    return __uint_as_float(u);
}
__device__ __forceinline__ void ldsm_x4(uint32_t r[4], uint32_t addr) {
    asm volatile("ldmatrix.sync.aligned.m8n8.x4.shared.b16 {%0,%1,%2,%3}, [%4];"
                 : "=r"(r[0]), "=r"(r[1]), "=r"(r[2]), "=r"(r[3]) : "r"(addr));
}
__device__ __forceinline__ void mma_tf32(float c[4], const uint32_t a[4],
                                         uint32_t b0, uint32_t b1) {
    asm volatile(
        "mma.sync.aligned.m16n8k8.row.col.f32.tf32.tf32.f32 "
        "{%0,%1,%2,%3},{%4,%5,%6,%7},{%8,%9},{%0,%1,%2,%3};"
        : "+f"(c[0]), "+f"(c[1]), "+f"(c[2]), "+f"(c[3])
        : "r"(a[0]), "r"(a[1]), "r"(a[2]), "r"(a[3]), "r"(b0), "r"(b1));
}

// ---------------- CSR build ----------------
__global__ void k_init_cnt() {
    int i = blockIdx.x * blockDim.x + threadIdx.x;
    if (i < NNODE) g_cnt[i] = 1;  // self-loop
}

__global__ void k_hist(const int* __restrict__ ei) {
    int e = blockIdx.x * blockDim.x + threadIdx.x;
    if (e < NEDGE) atomicAdd(&g_cnt[ei[NEDGE + e]], 1);  // dst row
}

__global__ void k_scan() {
    __shared__ int s[1024];
    int tid = threadIdx.x;
    int base = tid * 16;
    int v[16];
    int tot = 0;
#pragma unroll
    for (int j = 0; j < 16; j++) { v[j] = g_cnt[base + j]; tot += v[j]; }
    s[tid] = tot;
    __syncthreads();
    for (int o = 1; o < 1024; o <<= 1) {
        int add = (tid >= o) ? s[tid - o] : 0;
        __syncthreads();
        s[tid] += add;
        __syncthreads();
    }
    int run = (tid == 0) ? 0 : s[tid - 1];
#pragma unroll
    for (int j = 0; j < 16; j++) {
        g_rowptr[base + j] = run;
        g_off[base + j] = run;
        g_dinv[base + j] = rsqrtf((float)v[j]);
        run += v[j];
    }
    if (tid == 1023) g_rowptr[NNODE] = s[1023];
}

__global__ void k_scatter(const int* __restrict__ ei) {
    int idx = blockIdx.x * blockDim.x + threadIdx.x;
    if (idx >= NLOOP) return;
    int s, d;
    if (idx < NEDGE) { s = ei[idx]; d = ei[NEDGE + idx]; }
    else             { s = idx - NEDGE; d = s; }
    int p = atomicAdd(&g_off[d], 1);
    g_col[p] = s;
}

// ---------------- dense GEMM: C[M,NC] = A[M,K] @ W[K,NC] (+bias,relu) -------
template <int K, int NC, bool EPI>
__global__ void k_gemm_nn(const float* __restrict__ A, const float* __restrict__ W,
                          float* __restrict__ C, const float* __restrict__ bias) {
    __shared__ float As[32][68];
    __shared__ float Bs[32][64];
    const int tx = threadIdx.x & 15, ty = threadIdx.x >> 4;
    const int bm = blockIdx.y * 64, bn = blockIdx.x * 64;
    float acc[4][4] = {};
    for (int k0 = 0; k0 < K; k0 += 32) {
#pragma unroll
        for (int i = 0; i < 2; i++) {
            int idx = threadIdx.x + i * 256;
            int r = idx >> 3, kc = (idx & 7) * 4;
            float4 v = *(const float4*)&A[(bm + r) * K + k0 + kc];
            As[kc + 0][r] = v.x; As[kc + 1][r] = v.y;
            As[kc + 2][r] = v.z; As[kc + 3][r] = v.w;
        }
#pragma unroll
        for (int i = 0; i < 2; i++) {
            int idx = threadIdx.x + i * 256;
            int r = idx >> 4, c = (idx & 15) * 4;
            *(float4*)&Bs[r][c] = *(const float4*)&W[(k0 + r) * NC + bn + c];
        }
        __syncthreads();
#pragma unroll
        for (int kk = 0; kk < 32; kk++) {
            float a[4], b[4];
            *(float4*)a = *(const float4*)&As[kk][ty * 4];
            *(float4*)b = *(const float4*)&Bs[kk][tx * 4];
#pragma unroll
            for (int i = 0; i < 4; i++)
#pragma unroll
                for (int j = 0; j < 4; j++) acc[i][j] += a[i] * b[j];
        }
        __syncthreads();
    }
#pragma unroll
    for (int i = 0; i < 4; i++) {
        float4 o;
        float* po = (float*)&o;
#pragma unroll
        for (int j = 0; j < 4; j++) {
            float v = acc[i][j];
            if (EPI) v = fmaxf(v + bias[bn + tx * 4 + j], 0.f);
            po[j] = v;
        }
        *(float4*)&C[(bm + ty * 4 + i) * NC + bn + tx * 4] = o;
    }
}

// ---------------- CSR aggregation (+ optional bias + relu) ------------------
template <int F, bool BR>
__global__ void k_agg(const float* __restrict__ t, const float* __restrict__ bias,
                      float* __restrict__ out) {
    int warp = (blockIdx.x * blockDim.x + threadIdx.x) >> 5;
    int lane = threadIdx.x & 31;
    if (warp >= NNODE) return;
    int e = g_rowptr[warp], end = g_rowptr[warp + 1];
    float acc[F / 32] = {};
    for (; e < end; e++) {
        int s = __ldg(&g_col[e]);
        float w = __ldg(&g_dinv[s]);
        const float* row = t + s * F;
#pragma unroll
        for (int j = 0; j < F / 32; j++) acc[j] += w * __ldg(&row[lane + 32 * j]);
    }
    float di = __ldg(&g_dinv[warp]);
#pragma unroll
    for (int j = 0; j < F / 32; j++) {
        float v = acc[j] * di;
        if (BR) v = fmaxf(v + __ldg(&bias[lane + 32 * j]), 0.f);
        out[warp * F + lane + 32 * j] = v;
    }
}

// ---------------- z @ z.T via tf32 mma (symmetric, lower-tri compute) -------
// 128x128 tile per block, 8 warps (4x2), warp tile 32x64, K=64.
__global__ void k_zzt_mma(const float* __restrict__ Z, float* __restrict__ C) {
    const int ti = blockIdx.y, tj = blockIdx.x;
    if (tj > ti) return;
    extern __shared__ float sm[];
    float* Za = sm;              // [128][LDZ]
    float* Zb = sm + 128 * LDZ;  // [128][LDZ]
    const int tid = threadIdx.x;
    const int lane = tid & 31, warp = tid >> 5;
    const int wm = warp >> 1, wn = warp & 1;
    const int m0 = wm * 32, n0 = wn * 64;

#pragma unroll
    for (int i = 0; i < 8; i++) {
        int idx = tid + i * 256;  // 2048 float4s per tile
        int r = idx >> 4, c = (idx & 15) * 4;
        float4 va = *(const float4*)&Z[(ti * 128 + r) * 64 + c];
        float4 vb = *(const float4*)&Z[(tj * 128 + r) * 64 + c];
        Za[r * LDZ + c + 0] = to_tf32(va.x); Za[r * LDZ + c + 1] = to_tf32(va.y);
        Za[r * LDZ + c + 2] = to_tf32(va.z); Za[r * LDZ + c + 3] = to_tf32(va.w);
        Zb[r * LDZ + c + 0] = to_tf32(vb.x); Zb[r * LDZ + c + 1] = to_tf32(vb.y);
        Zb[r * LDZ + c + 2] = to_tf32(vb.z); Zb[r * LDZ + c + 3] = to_tf32(vb.w);
    }
    __syncthreads();

    uint32_t a_base = (uint32_t)__cvta_generic_to_shared(Za);
    uint32_t b_base = (uint32_t)__cvta_generic_to_shared(Zb);
    float acc[2][8][4] = {};
#pragma unroll
    for (int ks = 0; ks < 8; ks++) {
        const int k0 = ks * 8;
        uint32_t a[2][4];
#pragma unroll
        for (int f = 0; f < 2; f++) {
            int r = m0 + f * 16 + (lane & 7) + ((lane & 8) ? 8 : 0);
            int kk = k0 + ((lane & 16) ? 4 : 0);
            ldsm_x4(a[f], a_base + (uint32_t)(r * LDZ + kk) * 4u);
        }
        uint32_t b[4][4];  // pair p covers n-frags 2p (regs 0,1) and 2p+1 (regs 2,3)
#pragma unroll
        for (int p = 0; p < 4; p++) {
            int r = n0 + p * 16 + (lane & 7) + ((lane & 16) ? 8 : 0);
            int kk = k0 + ((lane & 8) ? 4 : 0);
            ldsm_x4(b[p], b_base + (uint32_t)(r * LDZ + kk) * 4u);
        }
#pragma unroll
        for (int f = 0; f < 2; f++)
#pragma unroll
            for (int j = 0; j < 8; j++)
                mma_tf32(acc[f][j], a[f], b[j >> 1][(j & 1) * 2], b[j >> 1][(j & 1) * 2 + 1]);
    }

    // direct write of tile (ti, tj)
    const int mrow = lane >> 2, ncol2 = (lane & 3) * 2;
#pragma unroll
    for (int f = 0; f < 2; f++) {
        int row0 = ti * 128 + m0 + f * 16 + mrow;
#pragma unroll
        for (int j = 0; j < 8; j++) {
            int col = tj * 128 + n0 + j * 8 + ncol2;
            *(float2*)&C[(size_t)row0 * NNODE + col] =
                make_float2(acc[f][j][0], acc[f][j][1]);
            *(float2*)&C[(size_t)(row0 + 8) * NNODE + col] =
                make_float2(acc[f][j][2], acc[f][j][3]);
        }
    }
    if (ti == tj) return;

    // mirror: stage in smem, write transposed tile (tj, ti) coalesced
    __syncthreads();
    float(*S)[130] = (float(*)[130])sm;  // 128x130 = 66560 B <= 69632 B
#pragma unroll
    for (int f = 0; f < 2; f++) {
        int r = m0 + f * 16 + mrow;
#pragma unroll
        for (int j = 0; j < 8; j++) {
            int c = n0 + j * 8 + ncol2;
            S[r][c] = acc[f][j][0];     S[r][c + 1] = acc[f][j][1];
            S[r + 8][c] = acc[f][j][2]; S[r + 8][c + 1] = acc[f][j][3];
        }
    }
    __syncthreads();
    const int tx = tid & 15, ty = tid >> 4;
#pragma unroll
    for (int i = 0; i < 8; i++) {
        int y = ty * 8 + i;
        float o[8];
#pragma unroll
        for (int j = 0; j < 8; j++) o[j] = S[tx * 8 + j][y];
        *(float4*)&C[(size_t)(tj * 128 + y) * NNODE + ti * 128 + tx * 8]     = *(float4*)o;
        *(float4*)&C[(size_t)(tj * 128 + y) * NNODE + ti * 128 + tx * 8 + 4] = *(float4*)(o + 4);
    }
}

// ---------------- launch ----------------------------------------------------
extern "C" void kernel_launch(void* const* d_in, const int* in_sizes, int n_in,
                              void* d_out, int out_size) {
    const float* x  = (const float*)d_in[0];
    const int*   ei = (const int*)d_in[1];
    const float* W1 = (const float*)d_in[2];
    const float* b1 = (const float*)d_in[3];
    const float* W2 = (const float*)d_in[4];
    const float* b2 = (const float*)d_in[5];
    const float* Wd = (const float*)d_in[6];
    const float* bd = (const float*)d_in[7];
    float* out = (float*)d_out;
    float* xhat = out + (size_t)NNODE * NNODE;

    float* t; cudaGetSymbolAddress((void**)&t, g_t);
    float* h; cudaGetSymbolAddress((void**)&h, g_h);
    float* z; cudaGetSymbolAddress((void**)&z, g_z);

    const int zzt_smem = 2 * 128 * LDZ * (int)sizeof(float);  // 69632
    cudaFuncSetAttribute(k_zzt_mma, cudaFuncAttributeMaxDynamicSharedMemorySize,
                         zzt_smem);

    // one-time side resources (no device memory)
    struct Res {
        cudaStream_t sB;
        cudaEvent_t evA, evB;
        Res() {
            cudaStreamCreateWithFlags(&sB, cudaStreamNonBlocking);
            cudaEventCreateWithFlags(&evA, cudaEventDisableTiming);
            cudaEventCreateWithFlags(&evB, cudaEventDisableTiming);
        }
    };
    static Res R;

    // ---- fork: CSR build on sB, concurrent with x@W1 on main stream ----
    // (both sides are small, touch disjoint data, and have no L2-resident
    //  reuse set to poison — unlike the decoder/zzt overlap, which regressed)
    cudaEventRecord(R.evA, 0);
    cudaStreamWaitEvent(R.sB, R.evA, 0);
    k_init_cnt<<<NNODE / 256, 256, 0, R.sB>>>();
    k_hist<<<NEDGE / 256, 256, 0, R.sB>>>(ei);
    k_scan<<<1, 1024, 0, R.sB>>>();
    k_scatter<<<(NLOOP + 255) / 256, 256, 0, R.sB>>>(ei);
    cudaEventRecord(R.evB, R.sB);

    k_gemm_nn<NIN, NHID, false><<<dim3(1, NNODE / 64), 256>>>(x, W1, t, nullptr);

    // ---- join: encoder chain needs CSR + t ----
    cudaStreamWaitEvent(0, R.evB, 0);
    k_agg<NHID, true><<<NNODE * 32 / 256, 256>>>(t, b1, h);
    k_gemm_nn<NHID, NHID, false><<<dim3(1, NNODE / 64), 256>>>(h, W2, t, nullptr);
    k_agg<NHID, true><<<NNODE * 32 / 256, 256>>>(t, b2, z);

    // decoder (serial — overlapping it with zzt thrashes L2 and regresses)
    k_agg<NHID, false><<<NNODE * 32 / 256, 256>>>(z, nullptr, t);
    k_gemm_nn<NHID, NIN, true><<<dim3(NIN / 64, NNODE / 64), 256>>>(t, Wd, xhat, bd);

    // structure decoder: out = z @ z.T (symmetric, tf32 tensor path)
    k_zzt_mma<<<dim3(NNODE / 128, NNODE / 128), 256, zzt_smem>>>(z, out);
}

// round 8
// speedup vs baseline: 1.3143x; 1.0880x over previous
#include <cuda_runtime.h>
#include <cuda_fp16.h>
#include <math.h>
#include <stdint.h>

#define NNODE 16384
#define NEDGE 1048576
#define NLOOP (NEDGE + NNODE)
#define NIN 256
#define NHID 64
#define ZH_LD 72   // halfs per smem row (144 B stride -> ldmatrix conflict-free)

// ---------------- scratch (static device memory; no runtime alloc) ----------
__device__ int    g_cnt[NNODE];
__device__ int    g_rowptr[NNODE + 1];
__device__ int    g_off[NNODE];
__device__ int    g_col[NLOOP];
__device__ float  g_dinv[NNODE];
__device__ float  g_t[NNODE * NIN];
__device__ float  g_h[NNODE * NHID];
__device__ float  g_z[NNODE * NHID];
__device__ __half g_zh[NNODE * NHID];

// ---------------- ptx helpers ----------------
__device__ __forceinline__ void ldsm_x4(uint32_t r[4], uint32_t addr) {
    asm volatile("ldmatrix.sync.aligned.m8n8.x4.shared.b16 {%0,%1,%2,%3}, [%4];"
                 : "=r"(r[0]), "=r"(r[1]), "=r"(r[2]), "=r"(r[3]) : "r"(addr));
}
__device__ __forceinline__ void mma_f16(float c[4], const uint32_t a[4],
                                        uint32_t b0, uint32_t b1) {
    asm volatile(
        "mma.sync.aligned.m16n8k16.row.col.f32.f16.f16.f32 "
        "{%0,%1,%2,%3},{%4,%5,%6,%7},{%8,%9},{%0,%1,%2,%3};"
        : "+f"(c[0]), "+f"(c[1]), "+f"(c[2]), "+f"(c[3])
        : "r"(a[0]), "r"(a[1]), "r"(a[2]), "r"(a[3]), "r"(b0), "r"(b1));
}

// ---------------- CSR build ----------------
__global__ void k_init_cnt() {
    int i = blockIdx.x * blockDim.x + threadIdx.x;
    if (i < NNODE) g_cnt[i] = 1;  // self-loop
}

__global__ void k_hist(const int* __restrict__ ei) {
    int e = blockIdx.x * blockDim.x + threadIdx.x;
    if (e < NEDGE) atomicAdd(&g_cnt[ei[NEDGE + e]], 1);  // dst row
}

__global__ void k_scan() {
    __shared__ int s[1024];
    int tid = threadIdx.x;
    int base = tid * 16;
    int v[16];
    int tot = 0;
#pragma unroll
    for (int j = 0; j < 16; j++) { v[j] = g_cnt[base + j]; tot += v[j]; }
    s[tid] = tot;
    __syncthreads();
    for (int o = 1; o < 1024; o <<= 1) {
        int add = (tid >= o) ? s[tid - o] : 0;
        __syncthreads();
        s[tid] += add;
        __syncthreads();
    }
    int run = (tid == 0) ? 0 : s[tid - 1];
#pragma unroll
    for (int j = 0; j < 16; j++) {
        g_rowptr[base + j] = run;
        g_off[base + j] = run;
        g_dinv[base + j] = rsqrtf((float)v[j]);
        run += v[j];
    }
    if (tid == 1023) g_rowptr[NNODE] = s[1023];
}

__global__ void k_scatter(const int* __restrict__ ei) {
    int idx = blockIdx.x * blockDim.x + threadIdx.x;
    if (idx >= NLOOP) return;
    int s, d;
    if (idx < NEDGE) { s = ei[idx]; d = ei[NEDGE + idx]; }
    else             { s = idx - NEDGE; d = s; }
    int p = atomicAdd(&g_off[d], 1);
    g_col[p] = s;
}

// ---------------- dense GEMM: C[M,NC] = A[M,K] @ W[K,NC] (+bias,relu) -------
template <int K, int NC, bool EPI>
__global__ void k_gemm_nn(const float* __restrict__ A, const float* __restrict__ W,
                          float* __restrict__ C, const float* __restrict__ bias) {
    __shared__ float As[32][68];
    __shared__ float Bs[32][64];
    const int tx = threadIdx.x & 15, ty = threadIdx.x >> 4;
    const int bm = blockIdx.y * 64, bn = blockIdx.x * 64;
    float acc[4][4] = {};
    for (int k0 = 0; k0 < K; k0 += 32) {
#pragma unroll
        for (int i = 0; i < 2; i++) {
            int idx = threadIdx.x + i * 256;
            int r = idx >> 3, kc = (idx & 7) * 4;
            float4 v = *(const float4*)&A[(bm + r) * K + k0 + kc];
            As[kc + 0][r] = v.x; As[kc + 1][r] = v.y;
            As[kc + 2][r] = v.z; As[kc + 3][r] = v.w;
        }
#pragma unroll
        for (int i = 0; i < 2; i++) {
            int idx = threadIdx.x + i * 256;
            int r = idx >> 4, c = (idx & 15) * 4;
            *(float4*)&Bs[r][c] = *(const float4*)&W[(k0 + r) * NC + bn + c];
        }
        __syncthreads();
#pragma unroll
        for (int kk = 0; kk < 32; kk++) {
            float a[4], b[4];
            *(float4*)a = *(const float4*)&As[kk][ty * 4];
            *(float4*)b = *(const float4*)&Bs[kk][tx * 4];
#pragma unroll
            for (int i = 0; i < 4; i++)
#pragma unroll
                for (int j = 0; j < 4; j++) acc[i][j] += a[i] * b[j];
        }
        __syncthreads();
    }
#pragma unroll
    for (int i = 0; i < 4; i++) {
        float4 o;
        float* po = (float*)&o;
#pragma unroll
        for (int j = 0; j < 4; j++) {
            float v = acc[i][j];
            if (EPI) v = fmaxf(v + bias[bn + tx * 4 + j], 0.f);
            po[j] = v;
        }
        *(float4*)&C[(bm + ty * 4 + i) * NC + bn + tx * 4] = o;
    }
}

// ---------------- CSR aggregation (+ optional bias + relu) ------------------
template <int F, bool BR>
__global__ void k_agg(const float* __restrict__ t, const float* __restrict__ bias,
                      float* __restrict__ out) {
    int warp = (blockIdx.x * blockDim.x + threadIdx.x) >> 5;
    int lane = threadIdx.x & 31;
    if (warp >= NNODE) return;
    int e = g_rowptr[warp], end = g_rowptr[warp + 1];
    float acc[F / 32] = {};
    for (; e < end; e++) {
        int s = __ldg(&g_col[e]);
        float w = __ldg(&g_dinv[s]);
        const float* row = t + s * F;
#pragma unroll
        for (int j = 0; j < F / 32; j++) acc[j] += w * __ldg(&row[lane + 32 * j]);
    }
    float di = __ldg(&g_dinv[warp]);
#pragma unroll
    for (int j = 0; j < F / 32; j++) {
        float v = acc[j] * di;
        if (BR) v = fmaxf(v + __ldg(&bias[lane + 32 * j]), 0.f);
        out[warp * F + lane + 32 * j] = v;
    }
}

// ---------------- z (fp32) -> zh (fp16) pre-pass ----------------------------
__global__ void k_z2h(const float* __restrict__ z, __half* __restrict__ zh) {
    int i = blockIdx.x * blockDim.x + threadIdx.x;  // over float2 pairs
    float2 v = *(const float2*)&z[(size_t)i * 2];
    *(__half2*)&zh[(size_t)i * 2] = __floats2half2_rn(v.x, v.y);
}

// ---------------- z @ z.T via fp16 mma (symmetric, lower-tri compute) -------
// 128x128 tile per block, 8 warps (4x2), warp tile 32x64, K=64 in 4 k16 steps.
__global__ void k_zzt_hmma(const __half* __restrict__ Zh, float* __restrict__ C) {
    const int ti = blockIdx.y, tj = blockIdx.x;
    if (tj > ti) return;
    extern __shared__ float sm[];
    __half* Za = (__half*)sm;                 // [128][ZH_LD]
    __half* Zb = (__half*)sm + 128 * ZH_LD;   // [128][ZH_LD]
    const int tid = threadIdx.x;
    const int lane = tid & 31, warp = tid >> 5;
    const int wm = warp >> 1, wn = warp & 1;
    const int m0 = wm * 32, n0 = wn * 64;

    // load tiles: 128 rows x 128 B each = 1024 uint4 per tile
#pragma unroll
    for (int i = 0; i < 4; i++) {
        int idx = tid + i * 256;
        int r = idx >> 3, c8 = (idx & 7) * 8;   // 8 halfs = 16 B
        uint4 va = *(const uint4*)&Zh[(size_t)(ti * 128 + r) * 64 + c8];
        uint4 vb = *(const uint4*)&Zh[(size_t)(tj * 128 + r) * 64 + c8];
        *(uint4*)&Za[r * ZH_LD + c8] = va;
        *(uint4*)&Zb[r * ZH_LD + c8] = vb;
    }
    __syncthreads();

    uint32_t a_base = (uint32_t)__cvta_generic_to_shared(Za);
    uint32_t b_base = (uint32_t)__cvta_generic_to_shared(Zb);
    float acc[2][8][4] = {};
#pragma unroll
    for (int ks = 0; ks < 4; ks++) {
        const int k0 = ks * 16;
        uint32_t a[2][4];
#pragma unroll
        for (int f = 0; f < 2; f++) {
            int r = m0 + f * 16 + (lane & 7) + ((lane & 8) ? 8 : 0);
            int kk = k0 + ((lane & 16) ? 8 : 0);
            ldsm_x4(a[f], a_base + (uint32_t)(r * ZH_LD + kk) * 2u);
        }
        uint32_t b[4][4];  // pair p: regs {b0(n),b1(n),b0(n+8),b1(n+8)}
#pragma unroll
        for (int p = 0; p < 4; p++) {
            int r = n0 + p * 16 + (lane & 7) + ((lane & 16) ? 8 : 0);
            int kk = k0 + ((lane & 8) ? 8 : 0);
            ldsm_x4(b[p], b_base + (uint32_t)(r * ZH_LD + kk) * 2u);
        }
#pragma unroll
        for (int f = 0; f < 2; f++)
#pragma unroll
            for (int j = 0; j < 8; j++)
                mma_f16(acc[f][j], a[f], b[j >> 1][(j & 1) * 2], b[j >> 1][(j & 1) * 2 + 1]);
    }

    // direct write of tile (ti, tj)
    const int mrow = lane >> 2, ncol2 = (lane & 3) * 2;
#pragma unroll
    for (int f = 0; f < 2; f++) {
        int row0 = ti * 128 + m0 + f * 16 + mrow;
#pragma unroll
        for (int j = 0; j < 8; j++) {
            int col = tj * 128 + n0 + j * 8 + ncol2;
            *(float2*)&C[(size_t)row0 * NNODE + col] =
                make_float2(acc[f][j][0], acc[f][j][1]);
            *(float2*)&C[(size_t)(row0 + 8) * NNODE + col] =
                make_float2(acc[f][j][2], acc[f][j][3]);
        }
    }
    if (ti == tj) return;

    // mirror: stage in smem, write transposed tile (tj, ti) coalesced
    __syncthreads();
    float(*S)[130] = (float(*)[130])sm;  // 128x130x4 = 66560 B
#pragma unroll
    for (int f = 0; f < 2; f++) {
        int r = m0 + f * 16 + mrow;
#pragma unroll
        for (int j = 0; j < 8; j++) {
            int c = n0 + j * 8 + ncol2;
            S[r][c] = acc[f][j][0];     S[r][c + 1] = acc[f][j][1];
            S[r + 8][c] = acc[f][j][2]; S[r + 8][c + 1] = acc[f][j][3];
        }
    }
    __syncthreads();
    const int tx = tid & 15, ty = tid >> 4;
#pragma unroll
    for (int i = 0; i < 8; i++) {
        int y = ty * 8 + i;
        float o[8];
#pragma unroll
        for (int j = 0; j < 8; j++) o[j] = S[tx * 8 + j][y];
        *(float4*)&C[(size_t)(tj * 128 + y) * NNODE + ti * 128 + tx * 8]     = *(float4*)o;
        *(float4*)&C[(size_t)(tj * 128 + y) * NNODE + ti * 128 + tx * 8 + 4] = *(float4*)(o + 4);
    }
}

// ---------------- launch ----------------------------------------------------
extern "C" void kernel_launch(void* const* d_in, const int* in_sizes, int n_in,
                              void* d_out, int out_size) {
    const float* x  = (const float*)d_in[0];
    const int*   ei = (const int*)d_in[1];
    const float* W1 = (const float*)d_in[2];
    const float* b1 = (const float*)d_in[3];
    const float* W2 = (const float*)d_in[4];
    const float* b2 = (const float*)d_in[5];
    const float* Wd = (const float*)d_in[6];
    const float* bd = (const float*)d_in[7];
    float* out = (float*)d_out;
    float* xhat = out + (size_t)NNODE * NNODE;

    float*  t;  cudaGetSymbolAddress((void**)&t,  g_t);
    float*  h;  cudaGetSymbolAddress((void**)&h,  g_h);
    float*  z;  cudaGetSymbolAddress((void**)&z,  g_z);
    __half* zh; cudaGetSymbolAddress((void**)&zh, g_zh);

    const int zzt_smem = 128 * 130 * (int)sizeof(float);  // 66560 (>= 2*128*ZH_LD*2)
    cudaFuncSetAttribute(k_zzt_hmma, cudaFuncAttributeMaxDynamicSharedMemorySize,
                         zzt_smem);

    // one-time side resources (no device memory)
    struct Res {
        cudaStream_t sB;
        cudaEvent_t evA, evB;
        Res() {
            cudaStreamCreateWithFlags(&sB, cudaStreamNonBlocking);
            cudaEventCreateWithFlags(&evA, cudaEventDisableTiming);
            cudaEventCreateWithFlags(&evB, cudaEventDisableTiming);
        }
    };
    static Res R;

    // ---- fork: CSR build on sB, concurrent with x@W1 on main stream ----
    cudaEventRecord(R.evA, 0);
    cudaStreamWaitEvent(R.sB, R.evA, 0);
    k_init_cnt<<<NNODE / 256, 256, 0, R.sB>>>();
    k_hist<<<NEDGE / 256, 256, 0, R.sB>>>(ei);
    k_scan<<<1, 1024, 0, R.sB>>>();
    k_scatter<<<(NLOOP + 255) / 256, 256, 0, R.sB>>>(ei);
    cudaEventRecord(R.evB, R.sB);

    k_gemm_nn<NIN, NHID, false><<<dim3(1, NNODE / 64), 256>>>(x, W1, t, nullptr);

    // ---- join: encoder chain needs CSR + t ----
    cudaStreamWaitEvent(0, R.evB, 0);
    k_agg<NHID, true><<<NNODE * 32 / 256, 256>>>(t, b1, h);
    k_gemm_nn<NHID, NHID, false><<<dim3(1, NNODE / 64), 256>>>(h, W2, t, nullptr);
    k_agg<NHID, true><<<NNODE * 32 / 256, 256>>>(t, b2, z);

    // z -> fp16 pre-pass for the structure decoder
    k_z2h<<<NNODE * NHID / 2 / 256, 256>>>(z, zh);

    // decoder (serial — overlapping it with zzt thrashes L2 and regresses)
    k_agg<NHID, false><<<NNODE * 32 / 256, 256>>>(z, nullptr, t);
    k_gemm_nn<NHID, NIN, true><<<dim3(NIN / 64, NNODE / 64), 256>>>(t, Wd, xhat, bd);

    // structure decoder: out = z @ z.T (symmetric, fp16 tensor path, f32 accum)
    k_zzt_hmma<<<dim3(NNODE / 128, NNODE / 128), 256, zzt_smem>>>(zh, out);
}

// round 9
// speedup vs baseline: 1.6409x; 1.2485x over previous
#include <cuda_runtime.h>
#include <cuda_fp16.h>
#include <math.h>
#include <stdint.h>

#define NNODE 16384
#define NEDGE 1048576
#define NLOOP (NEDGE + NNODE)
#define NIN 256
#define NHID 64
#define ZH_LD 72    // halfs per smem row (144 B stride -> ldmatrix conflict-free)
#define LDST 129    // staging stride (mod 32 == 1 -> transposed reads conflict-free)

// ---------------- scratch (static device memory; no runtime alloc) ----------
__device__ int    g_cnt[NNODE];
__device__ int    g_rowptr[NNODE + 1];
__device__ int    g_off[NNODE];
__device__ int    g_col[NLOOP];
__device__ float  g_dinv[NNODE];
__device__ float  g_t[NNODE * NIN];
__device__ float  g_h[NNODE * NHID];
__device__ float  g_z[NNODE * NHID];
__device__ __half g_zh[NNODE * NHID];

// ---------------- ptx helpers ----------------
__device__ __forceinline__ void ldsm_x4(uint32_t r[4], uint32_t addr) {
    asm volatile("ldmatrix.sync.aligned.m8n8.x4.shared.b16 {%0,%1,%2,%3}, [%4];"
                 : "=r"(r[0]), "=r"(r[1]), "=r"(r[2]), "=r"(r[3]) : "r"(addr));
}
__device__ __forceinline__ void mma_f16(float c[4], const uint32_t a[4],
                                        uint32_t b0, uint32_t b1) {
    asm volatile(
        "mma.sync.aligned.m16n8k16.row.col.f32.f16.f16.f32 "
        "{%0,%1,%2,%3},{%4,%5,%6,%7},{%8,%9},{%0,%1,%2,%3};"
        : "+f"(c[0]), "+f"(c[1]), "+f"(c[2]), "+f"(c[3])
        : "r"(a[0]), "r"(a[1]), "r"(a[2]), "r"(a[3]), "r"(b0), "r"(b1));
}

// ---------------- CSR build ----------------
__global__ void k_init_cnt() {
    int i = blockIdx.x * blockDim.x + threadIdx.x;
    if (i < NNODE) g_cnt[i] = 1;  // self-loop
}

__global__ void k_hist(const int* __restrict__ ei) {
    int e = blockIdx.x * blockDim.x + threadIdx.x;
    if (e < NEDGE) atomicAdd(&g_cnt[ei[NEDGE + e]], 1);  // dst row
}

__global__ void k_scan() {
    __shared__ int s[1024];
    int tid = threadIdx.x;
    int base = tid * 16;
    int v[16];
    int tot = 0;
#pragma unroll
    for (int j = 0; j < 16; j++) { v[j] = g_cnt[base + j]; tot += v[j]; }
    s[tid] = tot;
    __syncthreads();
    for (int o = 1; o < 1024; o <<= 1) {
        int add = (tid >= o) ? s[tid - o] : 0;
        __syncthreads();
        s[tid] += add;
        __syncthreads();
    }
    int run = (tid == 0) ? 0 : s[tid - 1];
#pragma unroll
    for (int j = 0; j < 16; j++) {
        g_rowptr[base + j] = run;
        g_off[base + j] = run;
        g_dinv[base + j] = rsqrtf((float)v[j]);
        run += v[j];
    }
    if (tid == 1023) g_rowptr[NNODE] = s[1023];
}

__global__ void k_scatter(const int* __restrict__ ei) {
    int idx = blockIdx.x * blockDim.x + threadIdx.x;
    if (idx >= NLOOP) return;
    int s, d;
    if (idx < NEDGE) { s = ei[idx]; d = ei[NEDGE + idx]; }
    else             { s = idx - NEDGE; d = s; }
    int p = atomicAdd(&g_off[d], 1);
    g_col[p] = s;
}

// ---------------- dense GEMM: C[M,NC] = A[M,K] @ W[K,NC] (+bias,relu) -------
template <int K, int NC, bool EPI>
__global__ void k_gemm_nn(const float* __restrict__ A, const float* __restrict__ W,
                          float* __restrict__ C, const float* __restrict__ bias) {
    __shared__ float As[32][68];
    __shared__ float Bs[32][64];
    const int tx = threadIdx.x & 15, ty = threadIdx.x >> 4;
    const int bm = blockIdx.y * 64, bn = blockIdx.x * 64;
    float acc[4][4] = {};
    for (int k0 = 0; k0 < K; k0 += 32) {
#pragma unroll
        for (int i = 0; i < 2; i++) {
            int idx = threadIdx.x + i * 256;
            int r = idx >> 3, kc = (idx & 7) * 4;
            float4 v = *(const float4*)&A[(bm + r) * K + k0 + kc];
            As[kc + 0][r] = v.x; As[kc + 1][r] = v.y;
            As[kc + 2][r] = v.z; As[kc + 3][r] = v.w;
        }
#pragma unroll
        for (int i = 0; i < 2; i++) {
            int idx = threadIdx.x + i * 256;
            int r = idx >> 4, c = (idx & 15) * 4;
            *(float4*)&Bs[r][c] = *(const float4*)&W[(k0 + r) * NC + bn + c];
        }
        __syncthreads();
#pragma unroll
        for (int kk = 0; kk < 32; kk++) {
            float a[4], b[4];
            *(float4*)a = *(const float4*)&As[kk][ty * 4];
            *(float4*)b = *(const float4*)&Bs[kk][tx * 4];
#pragma unroll
            for (int i = 0; i < 4; i++)
#pragma unroll
                for (int j = 0; j < 4; j++) acc[i][j] += a[i] * b[j];
        }
        __syncthreads();
    }
#pragma unroll
    for (int i = 0; i < 4; i++) {
        float4 o;
        float* po = (float*)&o;
#pragma unroll
        for (int j = 0; j < 4; j++) {
            float v = acc[i][j];
            if (EPI) v = fmaxf(v + bias[bn + tx * 4 + j], 0.f);
            po[j] = v;
        }
        *(float4*)&C[(bm + ty * 4 + i) * NC + bn + tx * 4] = o;
    }
}

// ---------------- CSR aggregation (+ optional bias + relu) ------------------
template <int F, bool BR>
__global__ void k_agg(const float* __restrict__ t, const float* __restrict__ bias,
                      float* __restrict__ out) {
    int warp = (blockIdx.x * blockDim.x + threadIdx.x) >> 5;
    int lane = threadIdx.x & 31;
    if (warp >= NNODE) return;
    int e = g_rowptr[warp], end = g_rowptr[warp + 1];
    float acc[F / 32] = {};
    for (; e < end; e++) {
        int s = __ldg(&g_col[e]);
        float w = __ldg(&g_dinv[s]);
        const float* row = t + s * F;
#pragma unroll
        for (int j = 0; j < F / 32; j++) acc[j] += w * __ldg(&row[lane + 32 * j]);
    }
    float di = __ldg(&g_dinv[warp]);
#pragma unroll
    for (int j = 0; j < F / 32; j++) {
        float v = acc[j] * di;
        if (BR) v = fmaxf(v + __ldg(&bias[lane + 32 * j]), 0.f);
        out[warp * F + lane + 32 * j] = v;
    }
}

// ---------------- z (fp32) -> zh (fp16) pre-pass ----------------------------
__global__ void k_z2h(const float* __restrict__ z, __half* __restrict__ zh) {
    int i = blockIdx.x * blockDim.x + threadIdx.x;  // over float2 pairs
    float2 v = *(const float2*)&z[(size_t)i * 2];
    *(__half2*)&zh[(size_t)i * 2] = __floats2half2_rn(v.x, v.y);
}

// ---------------- z @ z.T via fp16 mma (symmetric, lower-tri compute) -------
// 128x128 tile per block, 8 warps (4x2), warp tile 32x64, K=64 in 4 k16 steps.
__global__ void k_zzt_hmma(const __half* __restrict__ Zh, float* __restrict__ C) {
    const int ti = blockIdx.y, tj = blockIdx.x;
    if (tj > ti) return;
    extern __shared__ float sm[];
    __half* Za = (__half*)sm;                 // [128][ZH_LD]
    __half* Zb = (__half*)sm + 128 * ZH_LD;   // [128][ZH_LD]
    const int tid = threadIdx.x;
    const int lane = tid & 31, warp = tid >> 5;
    const int wm = warp >> 1, wn = warp & 1;
    const int m0 = wm * 32, n0 = wn * 64;

    // load tiles: 128 rows x 128 B each = 1024 uint4 per tile
#pragma unroll
    for (int i = 0; i < 4; i++) {
        int idx = tid + i * 256;
        int r = idx >> 3, c8 = (idx & 7) * 8;   // 8 halfs = 16 B
        uint4 va = *(const uint4*)&Zh[(size_t)(ti * 128 + r) * 64 + c8];
        uint4 vb = *(const uint4*)&Zh[(size_t)(tj * 128 + r) * 64 + c8];
        *(uint4*)&Za[r * ZH_LD + c8] = va;
        *(uint4*)&Zb[r * ZH_LD + c8] = vb;
    }
    __syncthreads();

    uint32_t a_base = (uint32_t)__cvta_generic_to_shared(Za);
    uint32_t b_base = (uint32_t)__cvta_generic_to_shared(Zb);
    float acc[2][8][4] = {};
#pragma unroll
    for (int ks = 0; ks < 4; ks++) {
        const int k0 = ks * 16;
        uint32_t a[2][4];
#pragma unroll
        for (int f = 0; f < 2; f++) {
            int r = m0 + f * 16 + (lane & 7) + ((lane & 8) ? 8 : 0);
            int kk = k0 + ((lane & 16) ? 8 : 0);
            ldsm_x4(a[f], a_base + (uint32_t)(r * ZH_LD + kk) * 2u);
        }
        uint32_t b[4][4];  // pair p: regs {b0(n),b1(n),b0(n+8),b1(n+8)}
#pragma unroll
        for (int p = 0; p < 4; p++) {
            int r = n0 + p * 16 + (lane & 7) + ((lane & 16) ? 8 : 0);
            int kk = k0 + ((lane & 8) ? 8 : 0);
            ldsm_x4(b[p], b_base + (uint32_t)(r * ZH_LD + kk) * 2u);
        }
#pragma unroll
        for (int f = 0; f < 2; f++)
#pragma unroll
            for (int j = 0; j < 8; j++)
                mma_f16(acc[f][j], a[f], b[j >> 1][(j & 1) * 2], b[j >> 1][(j & 1) * 2 + 1]);
    }

    // direct write of tile (ti, tj): straight from registers, coalesces in L2
    const int mrow = lane >> 2, ncol2 = (lane & 3) * 2;
#pragma unroll
    for (int f = 0; f < 2; f++) {
        int row0 = ti * 128 + m0 + f * 16 + mrow;
#pragma unroll
        for (int j = 0; j < 8; j++) {
            int col = tj * 128 + n0 + j * 8 + ncol2;
            *(float2*)&C[(size_t)row0 * NNODE + col] =
                make_float2(acc[f][j][0], acc[f][j][1]);
            *(float2*)&C[(size_t)(row0 + 8) * NNODE + col] =
                make_float2(acc[f][j][2], acc[f][j][3]);
        }
    }
    if (ti == tj) return;

    // mirror tile (tj, ti): stage with stride LDST=129 (mod 32 == 1) so the
    // transposed reads are bank-conflict-free; scalar coalesced global stores.
    __syncthreads();
    float* S = sm;  // 128 * 129 floats = 66048 B
#pragma unroll
    for (int f = 0; f < 2; f++) {
        int r = m0 + f * 16 + mrow;
#pragma unroll
        for (int j = 0; j < 8; j++) {
            int c = n0 + j * 8 + ncol2;
            S[r * LDST + c] = acc[f][j][0];
            S[r * LDST + c + 1] = acc[f][j][1];
            S[(r + 8) * LDST + c] = acc[f][j][2];
            S[(r + 8) * LDST + c + 1] = acc[f][j][3];
        }
    }
    __syncthreads();
    // warp w handles rows y = w*16 .. w*16+15; lane covers cols lane+32k.
    // read bank = (lane + y) mod 32 -> conflict-free; store = 128B/instr coalesced.
#pragma unroll
    for (int i = 0; i < 16; i++) {
        int y = warp * 16 + i;
        size_t rowbase = (size_t)(tj * 128 + y) * NNODE + ti * 128;
#pragma unroll
        for (int k = 0; k < 4; k++) {
            int col = lane + 32 * k;
            __stcs(&C[rowbase + col], S[col * LDST + y]);
        }
    }
}

// ---------------- launch ----------------------------------------------------
extern "C" void kernel_launch(void* const* d_in, const int* in_sizes, int n_in,
                              void* d_out, int out_size) {
    const float* x  = (const float*)d_in[0];
    const int*   ei = (const int*)d_in[1];
    const float* W1 = (const float*)d_in[2];
    const float* b1 = (const float*)d_in[3];
    const float* W2 = (const float*)d_in[4];
    const float* b2 = (const float*)d_in[5];
    const float* Wd = (const float*)d_in[6];
    const float* bd = (const float*)d_in[7];
    float* out = (float*)d_out;
    float* xhat = out + (size_t)NNODE * NNODE;

    float*  t;  cudaGetSymbolAddress((void**)&t,  g_t);
    float*  h;  cudaGetSymbolAddress((void**)&h,  g_h);
    float*  z;  cudaGetSymbolAddress((void**)&z,  g_z);
    __half* zh; cudaGetSymbolAddress((void**)&zh, g_zh);

    const int zzt_smem = 128 * LDST * (int)sizeof(float);  // 66048
    cudaFuncSetAttribute(k_zzt_hmma, cudaFuncAttributeMaxDynamicSharedMemorySize,
                         zzt_smem);

    // one-time side resources (no device memory)
    struct Res {
        cudaStream_t sB;
        cudaEvent_t evA, evB;
        Res() {
            cudaStreamCreateWithFlags(&sB, cudaStreamNonBlocking);
            cudaEventCreateWithFlags(&evA, cudaEventDisableTiming);
            cudaEventCreateWithFlags(&evB, cudaEventDisableTiming);
        }
    };
    static Res R;

    // ---- fork: CSR build on sB, concurrent with x@W1 on main stream ----
    cudaEventRecord(R.evA, 0);
    cudaStreamWaitEvent(R.sB, R.evA, 0);
    k_init_cnt<<<NNODE / 256, 256, 0, R.sB>>>();
    k_hist<<<NEDGE / 256, 256, 0, R.sB>>>(ei);
    k_scan<<<1, 1024, 0, R.sB>>>();
    k_scatter<<<(NLOOP + 255) / 256, 256, 0, R.sB>>>(ei);
    cudaEventRecord(R.evB, R.sB);

    k_gemm_nn<NIN, NHID, false><<<dim3(1, NNODE / 64), 256>>>(x, W1, t, nullptr);

    // ---- join: encoder chain needs CSR + t ----
    cudaStreamWaitEvent(0, R.evB, 0);
    k_agg<NHID, true><<<NNODE * 32 / 256, 256>>>(t, b1, h);
    k_gemm_nn<NHID, NHID, false><<<dim3(1, NNODE / 64), 256>>>(h, W2, t, nullptr);
    k_agg<NHID, true><<<NNODE * 32 / 256, 256>>>(t, b2, z);

    // z -> fp16 pre-pass for the structure decoder
    k_z2h<<<NNODE * NHID / 2 / 256, 256>>>(z, zh);

    // decoder (serial — overlapping it with zzt thrashes L2 and regresses)
    k_agg<NHID, false><<<NNODE * 32 / 256, 256>>>(z, nullptr, t);
    k_gemm_nn<NHID, NIN, true><<<dim3(NIN / 64, NNODE / 64), 256>>>(t, Wd, xhat, bd);

    // structure decoder: out = z @ z.T (symmetric, fp16 tensor path, f32 accum)
    k_zzt_hmma<<<dim3(NNODE / 128, NNODE / 128), 256, zzt_smem>>>(zh, out);
}